// round 4
// baseline (speedup 1.0000x reference)
#include <cuda_runtime.h>
#include <cstdint>

// ---------------------------------------------------------------------------
// SparseResUQueryNet: history sparse conv (1->32) + time max-pool + query
// sparse conv (32->32) evaluated per point.
//
// Keys pack into 28 bits: ((t*256+x)*256+y)*256+z  (t<16, coords in [1,250]).
// Pool keys pack into 25 bits (b<2). Deltas modify x/y/z bytes only; coords
// in [1,250] guarantee no byte carry, so nk stays in range for direct maps.
//
// R4: no hash tables. Direct-mapped dense feature array + compact pooled
// rows via a direct-mapped rowid table (atomicAdd allocation). Validity is
// gated by exact occupancy bitmaps; only touched bitmap/rowid words are
// cleared each launch (graph-replay deterministic).
// Total static footprint ~1.3 GB (fits AArch64 +-4GB relocation range).
// ---------------------------------------------------------------------------

#define FULL_MASK 0xFFFFFFFFu
#define BM1_WORDS (1u << 23)   // 2^28 bits = 32 MB  (t,x,y,z occupancy)
#define BM2_WORDS (1u << 20)   // 2^25 bits = 4 MB   (b,x,y,z occupancy)
#define ROW_CAP   (1u << 20)   // >= unique pool cells (~634k)

// Static scratch (no cudaMalloc allowed). Zero .bss at module load.
__device__ float    g_feat[1u << 28];                  // 1 GB   key -> feature
__device__ float    g_pooled[(size_t)ROW_CAP * 32];    // 128 MB compact rows
__device__ int      g_rowid[1u << 25];                 // 128 MB pk -> row
__device__ unsigned g_bm1[BM1_WORDS];                  // 32 MB
__device__ unsigned g_bm2[BM2_WORDS];                  // 4 MB
__device__ unsigned g_cont[BM2_WORDS];                 // 4 MB contested bits
__device__ int      g_row_cnt;

// delta[d] = (dx<<16)+(dy<<8)+dz for d = (dx+1)*9+(dy+1)*3+(dz+1)
__constant__ unsigned c_delta[27] = {
    0xFFFEFEFFu, 0xFFFEFF00u, 0xFFFEFF01u,
    0xFFFEFFFFu, 0xFFFF0000u, 0xFFFF0001u,
    0xFFFF00FFu, 0xFFFF0100u, 0xFFFF0101u,
    0xFFFFFEFFu, 0xFFFFFF00u, 0xFFFFFF01u,
    0xFFFFFFFFu, 0x00000000u, 0x00000001u,
    0x000000FFu, 0x00000100u, 0x00000101u,
    0x0000FEFFu, 0x0000FF00u, 0x0000FF01u,
    0x0000FFFFu, 0x00010000u, 0x00010001u,
    0x000100FFu, 0x00010100u, 0x00010101u
};

// Order-preserving float<->uint map (atomicMax pooling on contested rows).
// All real float encodings are >= 0x007FFFFF, so bits-0 is a safe identity.
__device__ __forceinline__ unsigned encf(float f) {
    unsigned b = __float_as_uint(f);
    return b ^ (unsigned)(((int)b >> 31) | 0x80000000);
}
__device__ __forceinline__ float decf(unsigned u) {
    unsigned x = ((int)u < 0) ? (u ^ 0x80000000u) : ~u;
    return __uint_as_float(x);
}
__device__ __forceinline__ bool bit_test(const unsigned* bm, unsigned idx) {
    return (bm[idx >> 5] >> (idx & 31)) & 1u;
}

// ---------------------------------------------------------------------------
// K0: scatter-clear ONLY the words this input touches. Stale g_feat/g_pooled
// contents are never read (bitmap-gated) or are fully overwritten.
// ---------------------------------------------------------------------------
__global__ void k_clear(const int4* __restrict__ hcoord,
                        const int* __restrict__ hbatch, int n) {
    int i = blockIdx.x * blockDim.x + threadIdx.x;
    if (i >= n) return;
    int4 c = hcoord[i];  // t, x, y, z
    unsigned key = ((unsigned)c.x << 24) | ((unsigned)c.y << 16) |
                   ((unsigned)c.z << 8) | (unsigned)c.w;
    unsigned pk = ((unsigned)hbatch[i] << 24) | ((unsigned)c.y << 16) |
                  ((unsigned)c.z << 8) | (unsigned)c.w;
    g_bm1[key >> 5] = 0u;
    g_bm2[pk >> 5] = 0u;
    g_cont[pk >> 5] = 0u;
    g_rowid[pk] = -1;
    if (i == 0) g_row_cnt = 0;
}

// ---------------------------------------------------------------------------
// K1: set occupancy bits, write feature direct-mapped. First arrival at a
// pool key allocates its compact row (atomicAdd) and publishes it; duplicate
// arrivals (contested cells, ~5k) set the contested bit, wait for the
// publication (publisher is already resident: it executed its atomicOr
// before ours returned the set bit), and zero the row (encoded minimum).
// ---------------------------------------------------------------------------
__global__ void k_insert(const float* __restrict__ hfeat,
                         const int4* __restrict__ hcoord,
                         const int* __restrict__ hbatch, int n) {
    int i = blockIdx.x * blockDim.x + threadIdx.x;
    if (i >= n) return;
    int4 c = hcoord[i];  // t, x, y, z
    unsigned key = ((unsigned)c.x << 24) | ((unsigned)c.y << 16) |
                   ((unsigned)c.z << 8) | (unsigned)c.w;
    atomicOr(&g_bm1[key >> 5], 1u << (key & 31));
    g_feat[key] = hfeat[i];  // history keys unique (np.unique upstream)
    unsigned pk = ((unsigned)hbatch[i] << 24) | ((unsigned)c.y << 16) |
                  ((unsigned)c.z << 8) | (unsigned)c.w;
    unsigned bit = 1u << (pk & 31);
    unsigned prev = atomicOr(&g_bm2[pk >> 5], bit);
    if (!(prev & bit)) {  // first arrival: allocate + publish row
        int row = atomicAdd(&g_row_cnt, 1);
        atomicExch(&g_rowid[pk], row);
    } else {              // duplicate: contested cell
        atomicOr(&g_cont[pk >> 5], bit);
        int row;
        do { row = atomicAdd(&g_rowid[pk], 0); } while (row < 0);
        float* r = &g_pooled[(size_t)row * 32];
#pragma unroll
        for (int q = 0; q < 32; q++) r[q] = 0.0f;  // bits 0 = encoded minimum
    }
}

// ---------------------------------------------------------------------------
// K2: one warp per history voxel. bb[w][lane] = sum_d f_d * Wbb[d][lane];
// membership via bm1 (27 lanes -> ~9 L1 wavefronts), feature loaded direct
// on hit (~1.07 hits/voxel). Max-pool into the compact row: plain coalesced
// float store if single-writer, atomicMax(encoded) if contested.
// ---------------------------------------------------------------------------
__global__ void k_bb_pool(const float* __restrict__ Wbb,
                          const int4* __restrict__ hcoord,
                          const int* __restrict__ hbatch, int n) {
    int w = (int)((blockIdx.x * blockDim.x + threadIdx.x) >> 5);
    int lane = threadIdx.x & 31;
    if (w >= n) return;
    int4 c = hcoord[w];
    unsigned key = ((unsigned)c.x << 24) | ((unsigned)c.y << 16) |
                   ((unsigned)c.z << 8) | (unsigned)c.w;
    float f = 0.0f;
    bool valid = false;
    if (lane < 27) {
        unsigned nk = key + c_delta[lane];
        if (bit_test(g_bm1, nk)) { f = g_feat[nk]; valid = true; }
    }
    unsigned m = __ballot_sync(FULL_MASK, valid);
    float acc = 0.0f;
    while (m) {  // ascending d == reference accumulation order
        int d = __ffs(m) - 1;
        m &= m - 1;
        float fd = __shfl_sync(FULL_MASK, f, d);
        acc = fmaf(fd, Wbb[d * 32 + lane], acc);
    }
    unsigned pk = ((unsigned)hbatch[w] << 24) | ((unsigned)c.y << 16) |
                  ((unsigned)c.z << 8) | (unsigned)c.w;
    int row = g_rowid[pk];
    float* addr = &g_pooled[(size_t)row * 32 + lane];  // coalesced 128B row
    if (bit_test(g_cont, pk)) atomicMax((unsigned*)addr, encf(acc));
    else *addr = acc;  // single writer: plain float
}

// ---------------------------------------------------------------------------
// K3: one warp per query point. Lanes 0..26 test bm2 for the 27 neighbors
// (~2% hit rate, ~9 wavefronts). Per valid delta: load rowid (uniform),
// broadcast-load the pooled row, decode iff contested, accumulate the lane's
// channel with 32 FFMAs vs W_conv[d]. Write [pt0..3 | 32 features].
// ---------------------------------------------------------------------------
__global__ void k_query(const float* __restrict__ points,
                        const float* __restrict__ Wc,
                        const int4* __restrict__ qcoord,
                        float* __restrict__ out, int npts) {
    int p = (int)((blockIdx.x * blockDim.x + threadIdx.x) >> 5);
    int lane = threadIdx.x & 31;
    if (p >= npts) return;
    int4 c = qcoord[p];  // b, x, y, z
    unsigned key = ((unsigned)c.x << 24) | ((unsigned)c.y << 16) |
                   ((unsigned)c.z << 8) | (unsigned)c.w;
    unsigned nk = 0u;
    bool valid = false;
    if (lane < 27) {
        nk = key + c_delta[lane];
        valid = bit_test(g_bm2, nk);
    }
    unsigned m = __ballot_sync(FULL_MASK, valid);
    float acc = 0.0f;
    while (m) {
        int d = __ffs(m) - 1;
        m &= m - 1;
        unsigned rk = __shfl_sync(FULL_MASK, nk, d);
        int row = g_rowid[rk];             // uniform -> broadcast
        bool cont = bit_test(g_cont, rk);  // uniform -> broadcast
        const float4* prow = (const float4*)&g_pooled[(size_t)row * 32];
        float pv[32];
#pragma unroll
        for (int q = 0; q < 8; q++) {
            float4 v = prow[q];  // uniform address -> broadcast
            pv[q * 4 + 0] = v.x;
            pv[q * 4 + 1] = v.y;
            pv[q * 4 + 2] = v.z;
            pv[q * 4 + 3] = v.w;
        }
        if (cont) {  // rare: contested rows stored max-encoded
#pragma unroll
            for (int q = 0; q < 32; q++) pv[q] = decf(__float_as_uint(pv[q]));
        }
        const float* wb = Wc + d * 1024 + lane;
#pragma unroll
        for (int k = 0; k < 32; k++) acc = fmaf(pv[k], wb[k * 32], acc);
    }
    float* o = out + (size_t)p * 36;
    o[4 + lane] = acc;
    if (lane < 4) o[lane] = points[(size_t)p * 5 + lane];
}

// ---------------------------------------------------------------------------
extern "C" void kernel_launch(void* const* d_in, const int* in_sizes, int n_in,
                              void* d_out, int out_size) {
    const float* hfeat  = (const float*)d_in[0];
    const float* points = (const float*)d_in[1];
    const float* Wbb    = (const float*)d_in[2];
    const float* Wc     = (const float*)d_in[3];
    const int4*  hcoord = (const int4*)d_in[4];
    const int*   hbatch = (const int*)d_in[5];
    const int4*  qcoord = (const int4*)d_in[6];
    float* out = (float*)d_out;

    int n    = in_sizes[5];      // history voxel count
    int npts = in_sizes[6] / 4;  // query point count

    const int TB = 256;
    k_clear<<<(n + TB - 1) / TB, TB>>>(hcoord, hbatch, n);
    k_insert<<<(n + TB - 1) / TB, TB>>>(hfeat, hcoord, hbatch, n);
    {
        long long tw = (long long)n * 32;
        int blocks = (int)((tw + TB - 1) / TB);
        k_bb_pool<<<blocks, TB>>>(Wbb, hcoord, hbatch, n);
    }
    {
        long long tw = (long long)npts * 32;
        int blocks = (int)((tw + TB - 1) / TB);
        k_query<<<blocks, TB>>>(points, Wc, qcoord, out, npts);
    }
}

// round 5
// speedup vs baseline: 1.0204x; 1.0204x over previous
#include <cuda_runtime.h>
#include <cstdint>

// ---------------------------------------------------------------------------
// SparseResUQueryNet R5: history sparse conv (1->32) + time max-pool + query
// sparse conv (32->32) per point.
//
// Keys: 28-bit ((t*256+x)*256+y)*256+z, t<16, coords in [1,250] (no byte
// carry under +-1 offsets). Pool keys: 25-bit (b<2, batch byte).
//
// Tables (all L2-friendly):
//   bm1 32MB / bm2 4MB exact occupancy bitmaps (dz-triples share words)
//   H1: hash key->feature, 8MB keys + 8MB payload (probed ~45k times total;
//       the dominant self-hit reads hfeat[w] directly)
//   pooled: compact rows (rowid alloc by atomicAdd), rowOf[i] per-voxel cache
// Contested pool cells (~1%) detected via atomicOr return; stored max-encoded
// (order-preserving uint) and decoded on read.
// ---------------------------------------------------------------------------

#define FULL_MASK 0xFFFFFFFFu
#define H1_LOG 21
#define H1_SIZE (1u << H1_LOG)
#define H1_MASK (H1_SIZE - 1u)
#define EMPTY_KEY 0xFFFFFFFFu
#define BM1_WORDS (1u << 23)   // 2^28 bits = 32 MB (+ pad)
#define BM2_WORDS (1u << 20)   // 2^25 bits = 4 MB  (+ pad)
#define ROW_CAP   (1u << 20)
#define NMAX      (1u << 20)

__device__ unsigned g_h1_keys[H1_SIZE];               // 8 MB
__device__ float    g_h1_feat[H1_SIZE];               // 8 MB
__device__ unsigned g_bm1[BM1_WORDS + 2];             // 32 MB
__device__ unsigned g_bm2[BM2_WORDS + 2];             // 4 MB
__device__ unsigned g_cont[BM2_WORDS];                // 4 MB contested bits
__device__ int      g_rowid[1u << 25];                // 128 MB pk -> row
__device__ int      g_rowOf[NMAX];                    // 4 MB voxel -> row
__device__ float    g_pooled[(size_t)ROW_CAP * 32];   // 128 MB compact rows
__device__ int      g_row_cnt;

// delta[d] = (dx<<16)+(dy<<8)+dz for d = (dx+1)*9+(dy+1)*3+(dz+1)
__constant__ unsigned c_delta[27] = {
    0xFFFEFEFFu, 0xFFFEFF00u, 0xFFFEFF01u,
    0xFFFEFFFFu, 0xFFFF0000u, 0xFFFF0001u,
    0xFFFF00FFu, 0xFFFF0100u, 0xFFFF0101u,
    0xFFFFFEFFu, 0xFFFFFF00u, 0xFFFFFF01u,
    0xFFFFFFFFu, 0x00000000u, 0x00000001u,
    0x000000FFu, 0x00000100u, 0x00000101u,
    0x0000FEFFu, 0x0000FF00u, 0x0000FF01u,
    0x0000FFFFu, 0x00010000u, 0x00010001u,
    0x000100FFu, 0x00010100u, 0x00010101u
};

__device__ __forceinline__ unsigned hash1(unsigned k) {
    return (k * 2654435761u) >> (32 - H1_LOG);
}
__device__ __forceinline__ unsigned encf(float f) {
    unsigned b = __float_as_uint(f);
    return b ^ (unsigned)(((int)b >> 31) | 0x80000000);
}
__device__ __forceinline__ float decf(unsigned u) {
    unsigned x = ((int)u < 0) ? (u ^ 0x80000000u) : ~u;
    return __uint_as_float(x);
}
__device__ __forceinline__ bool bit_test(const unsigned* bm, unsigned idx) {
    return (bm[idx >> 5] >> (idx & 31)) & 1u;
}
// Test 3 consecutive bits (dz=-1,0,+1) starting at bit position nk_m.
__device__ __forceinline__ unsigned test3(const unsigned* bm, unsigned nk_m) {
    unsigned idx = nk_m >> 5, b = nk_m & 31;
    unsigned w0 = bm[idx], w1 = bm[idx + 1];
    unsigned long long v = ((unsigned long long)w1 << 32) | (unsigned long long)w0;
    return (unsigned)((v >> b) & 7ull);
}
// d held by this lane = lane-th set bit of mask (ascending).
__device__ __forceinline__ int nth_bit(unsigned mask, int lane) {
    unsigned mm = mask;
    for (int t = 0; t < lane; t++) mm &= mm - 1;
    return __ffs(mm) - 1;
}

// ---------------------------------------------------------------------------
// K0: sweep-clear H1 keys (8MB, cheap) + scatter-clear the bitmap/rowid words
// this input touches. Stale pooled/feat payloads are never read.
// ---------------------------------------------------------------------------
__global__ void k_clear(const int4* __restrict__ hcoord,
                        const int* __restrict__ hbatch, int n) {
    int i = blockIdx.x * blockDim.x + threadIdx.x;
    int stride = gridDim.x * blockDim.x;
    for (unsigned s = (unsigned)i; s < H1_SIZE; s += stride) g_h1_keys[s] = EMPTY_KEY;
    if (i >= n) return;
    int4 c = hcoord[i];  // t, x, y, z
    unsigned key = ((unsigned)c.x << 24) | ((unsigned)c.y << 16) |
                   ((unsigned)c.z << 8) | (unsigned)c.w;
    unsigned pk = ((unsigned)hbatch[i] << 24) | (key & 0x00FFFFFFu);
    g_bm1[key >> 5] = 0u;
    g_bm2[pk >> 5] = 0u;
    g_cont[pk >> 5] = 0u;
    g_rowid[pk] = -1;
    if (i == 0) g_row_cnt = 0;
}

// ---------------------------------------------------------------------------
// K1: set bm1 + insert (key,feature) into H1; set bm2; first arrival per pool
// cell allocates a compact row and publishes it; duplicates mark contested,
// spin for publication (publisher already resident), zero the row.
// ---------------------------------------------------------------------------
__global__ void k_insert(const float* __restrict__ hfeat,
                         const int4* __restrict__ hcoord,
                         const int* __restrict__ hbatch, int n) {
    int i = blockIdx.x * blockDim.x + threadIdx.x;
    if (i >= n) return;
    int4 c = hcoord[i];
    unsigned key = ((unsigned)c.x << 24) | ((unsigned)c.y << 16) |
                   ((unsigned)c.z << 8) | (unsigned)c.w;
    atomicOr(&g_bm1[key >> 5], 1u << (key & 31));
    unsigned s = hash1(key);
    while (true) {  // history keys unique (np.unique upstream)
        unsigned old = atomicCAS(&g_h1_keys[s], EMPTY_KEY, key);
        if (old == EMPTY_KEY) { g_h1_feat[s] = hfeat[i]; break; }
        s = (s + 1) & H1_MASK;
    }
    unsigned pk = ((unsigned)hbatch[i] << 24) | (key & 0x00FFFFFFu);
    unsigned bit = 1u << (pk & 31);
    unsigned prev = atomicOr(&g_bm2[pk >> 5], bit);
    int row;
    if (!(prev & bit)) {  // first arrival: allocate + publish
        row = atomicAdd(&g_row_cnt, 1);
        atomicExch(&g_rowid[pk], row);
    } else {              // duplicate: contested cell
        atomicOr(&g_cont[pk >> 5], bit);
        do { row = atomicAdd(&g_rowid[pk], 0); } while (row < 0);
        float* r = &g_pooled[(size_t)row * 32];
#pragma unroll
        for (int q = 0; q < 32; q++) r[q] = 0.0f;  // bits 0 = encoded minimum
    }
    g_rowOf[i] = row;
}

// ---------------------------------------------------------------------------
// K2: one warp per history voxel. Lanes 0..8 build the 27-bit validity mask
// via dz-triple tests of bm1. Lane i (< popc) resolves the i-th valid delta:
// self (d=13) reads hfeat[w], others probe H1 (~45k probes total). fma in
// ascending d (reference order). Pool store: plain if uncontested, else
// atomicMax(order-preserving encoding).
// ---------------------------------------------------------------------------
__global__ void __launch_bounds__(256, 6)
k_bb_pool(const float* __restrict__ hfeat,
          const float* __restrict__ Wbb,
          const int4* __restrict__ hcoord,
          const int* __restrict__ hbatch, int n) {
    int w = (int)((blockIdx.x * blockDim.x + threadIdx.x) >> 5);
    int lane = threadIdx.x & 31;
    if (w >= n) return;
    int4 c = hcoord[w];  // broadcast load
    unsigned key = ((unsigned)c.x << 24) | ((unsigned)c.y << 16) |
                   ((unsigned)c.z << 8) | (unsigned)c.w;
    unsigned tri = 0;
    if (lane < 9) tri = test3(g_bm1, key + c_delta[lane * 3]) << (lane * 3);
    unsigned mask = __reduce_or_sync(FULL_MASK, tri);  // bit 13 always set
    int nhit = __popc(mask);
    float f = 0.0f;
    int d = 0;
    if (lane < nhit) {
        d = nth_bit(mask, lane);
        if (d == 13) {
            f = hfeat[w];
        } else {
            unsigned nk = key + c_delta[d];
            unsigned s = hash1(nk);
            while (g_h1_keys[s] != nk) s = (s + 1) & H1_MASK;  // exact bitmap
            f = g_h1_feat[s];
        }
    }
    float acc = 0.0f;
    for (int i = 0; i < nhit; i++) {  // ascending d
        float fd = __shfl_sync(FULL_MASK, f, i);
        int di = __shfl_sync(FULL_MASK, d, i);
        acc = fmaf(fd, Wbb[di * 32 + lane], acc);
    }
    int row = g_rowOf[w];  // broadcast
    unsigned pk = ((unsigned)hbatch[w] << 24) | (key & 0x00FFFFFFu);
    float* addr = &g_pooled[(size_t)row * 32 + lane];  // coalesced 128B
    if (bit_test(g_cont, pk)) atomicMax((unsigned*)addr, encf(acc));
    else *addr = acc;
}

// ---------------------------------------------------------------------------
// K3: one warp per query point. Lanes 0..8 build the 27-bit mask from bm2
// (~42% of points have any hit). Lane i (< popc) resolves row + contested
// flag for the i-th valid delta. Per hit: broadcast row load (float4 x8),
// decode iff contested, accumulate lane channel against W_conv[d] (L1-hot).
// ---------------------------------------------------------------------------
__global__ void __launch_bounds__(256, 6)
k_query(const float* __restrict__ points,
        const float* __restrict__ Wc,
        const int4* __restrict__ qcoord,
        float* __restrict__ out, int npts) {
    int p = (int)((blockIdx.x * blockDim.x + threadIdx.x) >> 5);
    int lane = threadIdx.x & 31;
    if (p >= npts) return;
    int4 c = qcoord[p];  // broadcast
    unsigned key = ((unsigned)c.x << 24) | ((unsigned)c.y << 16) |
                   ((unsigned)c.z << 8) | (unsigned)c.w;
    unsigned tri = 0;
    if (lane < 9) tri = test3(g_bm2, key + c_delta[lane * 3]) << (lane * 3);
    unsigned mask = __reduce_or_sync(FULL_MASK, tri);
    float acc = 0.0f;
    int nhit = __popc(mask);
    if (nhit) {
        int d = 0, row = 0;
        bool cont = false;
        if (lane < nhit) {
            d = nth_bit(mask, lane);
            unsigned rk = key + c_delta[d];
            row = g_rowid[rk];
            cont = bit_test(g_cont, rk);
        }
        for (int i = 0; i < nhit; i++) {  // ascending d
            int rowi = __shfl_sync(FULL_MASK, row, i);
            int di = __shfl_sync(FULL_MASK, d, i);
            int conti = __shfl_sync(FULL_MASK, (int)cont, i);
            const float4* prow = (const float4*)&g_pooled[(size_t)rowi * 32];
            const float* wb = Wc + di * 1024 + lane;
#pragma unroll
            for (int q = 0; q < 8; q++) {
                float4 v = prow[q];  // uniform address -> broadcast
                if (conti) {
                    v.x = decf(__float_as_uint(v.x));
                    v.y = decf(__float_as_uint(v.y));
                    v.z = decf(__float_as_uint(v.z));
                    v.w = decf(__float_as_uint(v.w));
                }
                acc = fmaf(v.x, wb[(q * 4 + 0) * 32], acc);
                acc = fmaf(v.y, wb[(q * 4 + 1) * 32], acc);
                acc = fmaf(v.z, wb[(q * 4 + 2) * 32], acc);
                acc = fmaf(v.w, wb[(q * 4 + 3) * 32], acc);
            }
        }
    }
    float* o = out + (size_t)p * 36;
    o[4 + lane] = acc;
    if (lane < 4) o[lane] = points[(size_t)p * 5 + lane];
}

// ---------------------------------------------------------------------------
extern "C" void kernel_launch(void* const* d_in, const int* in_sizes, int n_in,
                              void* d_out, int out_size) {
    const float* hfeat  = (const float*)d_in[0];
    const float* points = (const float*)d_in[1];
    const float* Wbb    = (const float*)d_in[2];
    const float* Wc     = (const float*)d_in[3];
    const int4*  hcoord = (const int4*)d_in[4];
    const int*   hbatch = (const int*)d_in[5];
    const int4*  qcoord = (const int4*)d_in[6];
    float* out = (float*)d_out;

    int n    = in_sizes[5];      // history voxel count
    int npts = in_sizes[6] / 4;  // query point count

    const int TB = 256;
    int clr_work = n > (int)H1_SIZE ? n : (int)H1_SIZE;
    k_clear<<<(clr_work + TB - 1) / TB, TB>>>(hcoord, hbatch, n);
    k_insert<<<(n + TB - 1) / TB, TB>>>(hfeat, hcoord, hbatch, n);
    {
        long long tw = (long long)n * 32;
        k_bb_pool<<<(int)((tw + TB - 1) / TB), TB>>>(hfeat, Wbb, hcoord, hbatch, n);
    }
    {
        long long tw = (long long)npts * 32;
        k_query<<<(int)((tw + TB - 1) / TB), TB>>>(points, Wc, qcoord, out, npts);
    }
}

// round 6
// speedup vs baseline: 1.0937x; 1.0718x over previous
#include <cuda_runtime.h>
#include <cstdint>

// ---------------------------------------------------------------------------
// SparseResUQueryNet R6: rank-compaction design.
//
// Keys: 28-bit ((t*256+x)*256+y)*256+z, t<16, coords in [1,250] (no byte
// carry under +-1 offsets). Pool keys: 25-bit (batch byte, b<2).
//
// Exact occupancy bitmaps (bm1 32MB, bm2 4MB) + per-word popcount prefix
// arrays give every key a deterministic compact index:
//     rank(k) = prefix[k>>5] + popc(bm[k>>5] & ((1<<(k&31))-1))
// Features live at g_featC[rank1(key)] (4MB, L2-resident; no hash table).
// Pooled rows live at g_pooled[rank2(pk)*32] (81MB used; no rowid table).
// Contested pool cells (~1%) detected via atomicOr return; rows pre-zeroed
// and max-pooled via order-preserving-uint atomicMax, decoded on read.
// ---------------------------------------------------------------------------

#define FULL_MASK 0xFFFFFFFFu
#define BM1_WORDS (1u << 23)   // 2^28 bits = 32 MB
#define BM2_WORDS (1u << 20)   // 2^25 bits = 4 MB
#define CHUNK 4096
#define NBLK1 (BM1_WORDS / CHUNK)   // 2048
#define NBLK2 (BM2_WORDS / CHUNK)   // 256
#define NMAX  (1u << 20)

__device__ unsigned g_bm1[BM1_WORDS + 2];             // 32 MB (+zero pad)
__device__ unsigned g_bm2[BM2_WORDS + 2];             // 4 MB  (+zero pad)
__device__ unsigned g_cont[BM2_WORDS];                // 4 MB contested bits
__device__ unsigned g_pref1[BM1_WORDS];               // 32 MB word prefix
__device__ unsigned g_pref2[BM2_WORDS];               // 4 MB word prefix
__device__ unsigned g_bsum1[NBLK1];
__device__ unsigned g_bsum2[NBLK2];
__device__ float    g_featC[NMAX];                    // 4 MB rank1 -> feature
__device__ int      g_rowOf[NMAX];                    // 4 MB voxel -> row
__device__ float    g_pooled[(size_t)NMAX * 32];      // 128 MB rank2 rows

// delta[d] = (dx<<16)+(dy<<8)+dz for d = (dx+1)*9+(dy+1)*3+(dz+1)
__constant__ unsigned c_delta[27] = {
    0xFFFEFEFFu, 0xFFFEFF00u, 0xFFFEFF01u,
    0xFFFEFFFFu, 0xFFFF0000u, 0xFFFF0001u,
    0xFFFF00FFu, 0xFFFF0100u, 0xFFFF0101u,
    0xFFFFFEFFu, 0xFFFFFF00u, 0xFFFFFF01u,
    0xFFFFFFFFu, 0x00000000u, 0x00000001u,
    0x000000FFu, 0x00000100u, 0x00000101u,
    0x0000FEFFu, 0x0000FF00u, 0x0000FF01u,
    0x0000FFFFu, 0x00010000u, 0x00010001u,
    0x000100FFu, 0x00010100u, 0x00010101u
};

__device__ __forceinline__ unsigned encf(float f) {
    unsigned b = __float_as_uint(f);
    return b ^ (unsigned)(((int)b >> 31) | 0x80000000);
}
__device__ __forceinline__ float decf(unsigned u) {
    unsigned x = ((int)u < 0) ? (u ^ 0x80000000u) : ~u;
    return __uint_as_float(x);
}
// Test 3 consecutive bits (dz=-1,0,+1) starting at bit position nk_m.
__device__ __forceinline__ unsigned test3(const unsigned* bm, unsigned nk_m) {
    unsigned idx = nk_m >> 5, b = nk_m & 31;
    unsigned long long v =
        ((unsigned long long)bm[idx + 1] << 32) | (unsigned long long)bm[idx];
    return (unsigned)((v >> b) & 7ull);
}
__device__ __forceinline__ unsigned rank_of(const unsigned* bm,
                                            const unsigned* pref, unsigned k) {
    unsigned w = k >> 5, b = k & 31;
    return pref[w] + __popc(bm[w] & ((1u << b) - 1u));
}
// d held by this lane = lane-th set bit of mask (ascending).
__device__ __forceinline__ int nth_bit(unsigned mask, int lane) {
    unsigned mm = mask;
    for (int t = 0; t < lane; t++) mm &= mm - 1;
    return __ffs(mm) - 1;
}
// Exclusive block scan over 256 values (Hillis-Steele in shared).
__device__ __forceinline__ int block_scan_excl(int v, int tid) {
    __shared__ int sh[256];
    sh[tid] = v;
    __syncthreads();
    for (int off = 1; off < 256; off <<= 1) {
        int add = (tid >= off) ? sh[tid - off] : 0;
        __syncthreads();
        sh[tid] += add;
        __syncthreads();
    }
    int incl = sh[tid];
    __syncthreads();
    return incl - v;
}

// ---------------------------------------------------------------------------
// K0: scatter-clear only the bitmap words this input touches. prefix/bsum
// arrays are fully rewritten every launch; featC/pooled/rowOf are gated.
// ---------------------------------------------------------------------------
__global__ void k_clear(const int4* __restrict__ hcoord,
                        const int* __restrict__ hbatch, int n) {
    int i = blockIdx.x * blockDim.x + threadIdx.x;
    if (i >= n) return;
    int4 c = hcoord[i];  // t, x, y, z
    unsigned key = ((unsigned)c.x << 24) | ((unsigned)c.y << 16) |
                   ((unsigned)c.z << 8) | (unsigned)c.w;
    unsigned pk = ((unsigned)hbatch[i] << 24) | (key & 0x00FFFFFFu);
    g_bm1[key >> 5] = 0u;
    g_bm2[pk >> 5] = 0u;
    g_cont[pk >> 5] = 0u;
}

// ---------------------------------------------------------------------------
// K1: set occupancy bits; duplicate pool-key arrivals mark contested cells.
// ---------------------------------------------------------------------------
__global__ void k_setbits(const int4* __restrict__ hcoord,
                          const int* __restrict__ hbatch, int n) {
    int i = blockIdx.x * blockDim.x + threadIdx.x;
    if (i >= n) return;
    int4 c = hcoord[i];
    unsigned key = ((unsigned)c.x << 24) | ((unsigned)c.y << 16) |
                   ((unsigned)c.z << 8) | (unsigned)c.w;
    atomicOr(&g_bm1[key >> 5], 1u << (key & 31));
    unsigned pk = ((unsigned)hbatch[i] << 24) | (key & 0x00FFFFFFu);
    unsigned bit = 1u << (pk & 31);
    unsigned prev = atomicOr(&g_bm2[pk >> 5], bit);
    if (prev & bit) atomicOr(&g_cont[pk >> 5], bit);
}

// ---------------------------------------------------------------------------
// Scan pass A: per-chunk popcount sums (blocks [0,NBLK1) -> bm1, rest -> bm2).
// ---------------------------------------------------------------------------
__global__ void k_scanA() {
    int blk = blockIdx.x, tid = threadIdx.x;
    const uint4* bm;
    unsigned* bsum;
    int base;
    if (blk < NBLK1) { bm = (const uint4*)g_bm1; bsum = g_bsum1; base = blk; }
    else             { bm = (const uint4*)g_bm2; bsum = g_bsum2; base = blk - NBLK1; }
    size_t w4 = (size_t)base * (CHUNK / 4) + (size_t)tid * 4;
    int s = 0;
#pragma unroll
    for (int j = 0; j < 4; j++) {
        uint4 v = bm[w4 + j];
        s += __popc(v.x) + __popc(v.y) + __popc(v.z) + __popc(v.w);
    }
    __shared__ int sh[256];
    sh[tid] = s;
    __syncthreads();
    for (int off = 128; off; off >>= 1) {
        if (tid < off) sh[tid] += sh[tid + off];
        __syncthreads();
    }
    if (tid == 0) bsum[base] = (unsigned)sh[0];
}

// ---------------------------------------------------------------------------
// Scan pass B: single block turns both bsum arrays into exclusive prefixes.
// ---------------------------------------------------------------------------
__global__ void k_scanB() {
    int tid = threadIdx.x;
    unsigned loc[8];
    int s = 0;
#pragma unroll
    for (int j = 0; j < 8; j++) { loc[j] = g_bsum1[tid * 8 + j]; s += loc[j]; }
    int ex = block_scan_excl(s, tid);
#pragma unroll
    for (int j = 0; j < 8; j++) {
        unsigned v = loc[j];
        g_bsum1[tid * 8 + j] = (unsigned)ex;
        ex += (int)v;
    }
    __syncthreads();
    unsigned v2 = g_bsum2[tid];
    int ex2 = block_scan_excl((int)v2, tid);
    g_bsum2[tid] = (unsigned)ex2;
}

// ---------------------------------------------------------------------------
// Scan pass C: write per-word exclusive prefix (g_pref1 / g_pref2).
// ---------------------------------------------------------------------------
__global__ void k_scanC() {
    int blk = blockIdx.x, tid = threadIdx.x;
    const unsigned* bm;
    const unsigned* bsum;
    unsigned* pref;
    int base;
    if (blk < NBLK1) { bm = g_bm1; bsum = g_bsum1; pref = g_pref1; base = blk; }
    else             { bm = g_bm2; bsum = g_bsum2; pref = g_pref2; base = blk - NBLK1; }
    size_t w0 = (size_t)base * CHUNK + (size_t)tid * 16;
    unsigned wv[16];
    int s = 0;
#pragma unroll
    for (int j = 0; j < 16; j++) { wv[j] = bm[w0 + j]; s += __popc(wv[j]); }
    int ex = block_scan_excl(s, tid);
    unsigned run = bsum[base] + (unsigned)ex;
#pragma unroll
    for (int j = 0; j < 16; j++) { pref[w0 + j] = run; run += __popc(wv[j]); }
}

// ---------------------------------------------------------------------------
// K2: scatter features to rank order; cache each voxel's pooled row index;
// zero contested rows (idempotent, multiple writers write the same zeros).
// ---------------------------------------------------------------------------
__global__ void k_scatter(const float* __restrict__ hfeat,
                          const int4* __restrict__ hcoord,
                          const int* __restrict__ hbatch, int n) {
    int i = blockIdx.x * blockDim.x + threadIdx.x;
    if (i >= n) return;
    int4 c = hcoord[i];
    unsigned key = ((unsigned)c.x << 24) | ((unsigned)c.y << 16) |
                   ((unsigned)c.z << 8) | (unsigned)c.w;
    g_featC[rank_of(g_bm1, g_pref1, key)] = hfeat[i];
    unsigned pk = ((unsigned)hbatch[i] << 24) | (key & 0x00FFFFFFu);
    unsigned r2 = rank_of(g_bm2, g_pref2, pk);
    g_rowOf[i] = (int)r2;
    if ((g_cont[pk >> 5] >> (pk & 31)) & 1u) {
        float* r = &g_pooled[(size_t)r2 * 32];
#pragma unroll
        for (int q = 0; q < 32; q++) r[q] = 0.0f;  // bits 0 = encoded minimum
    }
}

// ---------------------------------------------------------------------------
// K3: one warp per history voxel. Lanes 0..8 build the 27-bit validity mask
// via dz-triple tests of bm1; hit lane i resolves the i-th delta: self reads
// hfeat[w], neighbors read g_featC[rank1] (4MB, L2). FFMA ascending d.
// Pool store at g_rowOf[w]: plain if uncontested, atomicMax(encoded) else.
// ---------------------------------------------------------------------------
__global__ void __launch_bounds__(256, 6)
k_bb_pool(const float* __restrict__ hfeat,
          const float* __restrict__ Wbb,
          const int4* __restrict__ hcoord,
          const int* __restrict__ hbatch, int n) {
    int w = (int)((blockIdx.x * blockDim.x + threadIdx.x) >> 5);
    int lane = threadIdx.x & 31;
    if (w >= n) return;
    int4 c = hcoord[w];  // broadcast
    unsigned key = ((unsigned)c.x << 24) | ((unsigned)c.y << 16) |
                   ((unsigned)c.z << 8) | (unsigned)c.w;
    unsigned tri = 0;
    if (lane < 9) tri = test3(g_bm1, key + c_delta[lane * 3]) << (lane * 3);
    unsigned mask = __reduce_or_sync(FULL_MASK, tri);  // bit 13 always set
    int nhit = __popc(mask);
    float f = 0.0f;
    int d = 0;
    if (lane < nhit) {
        d = nth_bit(mask, lane);
        if (d == 13) f = hfeat[w];
        else f = g_featC[rank_of(g_bm1, g_pref1, key + c_delta[d])];
    }
    float acc = 0.0f;
    for (int i = 0; i < nhit; i++) {  // ascending d == reference order
        float fd = __shfl_sync(FULL_MASK, f, i);
        int di = __shfl_sync(FULL_MASK, d, i);
        acc = fmaf(fd, Wbb[di * 32 + lane], acc);
    }
    int row = g_rowOf[w];  // broadcast
    unsigned pk = ((unsigned)hbatch[w] << 24) | (key & 0x00FFFFFFu);
    float* addr = &g_pooled[(size_t)row * 32 + lane];  // coalesced 128B
    if ((g_cont[pk >> 5] >> (pk & 31)) & 1u) atomicMax((unsigned*)addr, encf(acc));
    else *addr = acc;
}

// ---------------------------------------------------------------------------
// K4: one warp per query point. Lanes 0..8 build the 27-bit mask from bm2;
// hit lane i resolves row = rank2 (prefix 4MB L2 + bm2 word L1-hot) and the
// contested flag. Per hit: broadcast row (float4 x8), decode iff contested,
// accumulate lane channel against W_conv[d]. Write [pt0..3 | 32 features].
// ---------------------------------------------------------------------------
__global__ void __launch_bounds__(256, 6)
k_query(const float* __restrict__ points,
        const float* __restrict__ Wc,
        const int4* __restrict__ qcoord,
        float* __restrict__ out, int npts) {
    int p = (int)((blockIdx.x * blockDim.x + threadIdx.x) >> 5);
    int lane = threadIdx.x & 31;
    if (p >= npts) return;
    int4 c = qcoord[p];  // broadcast
    unsigned key = ((unsigned)c.x << 24) | ((unsigned)c.y << 16) |
                   ((unsigned)c.z << 8) | (unsigned)c.w;
    unsigned tri = 0;
    if (lane < 9) tri = test3(g_bm2, key + c_delta[lane * 3]) << (lane * 3);
    unsigned mask = __reduce_or_sync(FULL_MASK, tri);
    float acc = 0.0f;
    int nhit = __popc(mask);
    if (nhit) {
        int d = 0, row = 0;
        bool cont = false;
        if (lane < nhit) {
            d = nth_bit(mask, lane);
            unsigned rk = key + c_delta[d];
            row = (int)rank_of(g_bm2, g_pref2, rk);
            cont = (g_cont[rk >> 5] >> (rk & 31)) & 1u;
        }
        for (int i = 0; i < nhit; i++) {  // ascending d
            int rowi = __shfl_sync(FULL_MASK, row, i);
            int di = __shfl_sync(FULL_MASK, d, i);
            int conti = __shfl_sync(FULL_MASK, (int)cont, i);
            const float4* prow = (const float4*)&g_pooled[(size_t)rowi * 32];
            const float* wb = Wc + di * 1024 + lane;
#pragma unroll
            for (int q = 0; q < 8; q++) {
                float4 v = prow[q];  // uniform address -> broadcast
                if (conti) {
                    v.x = decf(__float_as_uint(v.x));
                    v.y = decf(__float_as_uint(v.y));
                    v.z = decf(__float_as_uint(v.z));
                    v.w = decf(__float_as_uint(v.w));
                }
                acc = fmaf(v.x, wb[(q * 4 + 0) * 32], acc);
                acc = fmaf(v.y, wb[(q * 4 + 1) * 32], acc);
                acc = fmaf(v.z, wb[(q * 4 + 2) * 32], acc);
                acc = fmaf(v.w, wb[(q * 4 + 3) * 32], acc);
            }
        }
    }
    float* o = out + (size_t)p * 36;
    o[4 + lane] = acc;
    if (lane < 4) o[lane] = points[(size_t)p * 5 + lane];
}

// ---------------------------------------------------------------------------
extern "C" void kernel_launch(void* const* d_in, const int* in_sizes, int n_in,
                              void* d_out, int out_size) {
    const float* hfeat  = (const float*)d_in[0];
    const float* points = (const float*)d_in[1];
    const float* Wbb    = (const float*)d_in[2];
    const float* Wc     = (const float*)d_in[3];
    const int4*  hcoord = (const int4*)d_in[4];
    const int*   hbatch = (const int*)d_in[5];
    const int4*  qcoord = (const int4*)d_in[6];
    float* out = (float*)d_out;

    int n    = in_sizes[5];      // history voxel count
    int npts = in_sizes[6] / 4;  // query point count

    const int TB = 256;
    int nb = (n + TB - 1) / TB;
    k_clear<<<nb, TB>>>(hcoord, hbatch, n);
    k_setbits<<<nb, TB>>>(hcoord, hbatch, n);
    k_scanA<<<NBLK1 + NBLK2, TB>>>();
    k_scanB<<<1, TB>>>();
    k_scanC<<<NBLK1 + NBLK2, TB>>>();
    k_scatter<<<nb, TB>>>(hfeat, hcoord, hbatch, n);
    {
        long long tw = (long long)n * 32;
        k_bb_pool<<<(int)((tw + TB - 1) / TB), TB>>>(hfeat, Wbb, hcoord, hbatch, n);
    }
    {
        long long tw = (long long)npts * 32;
        k_query<<<(int)((tw + TB - 1) / TB), TB>>>(points, Wc, qcoord, out, npts);
    }
}

// round 7
// speedup vs baseline: 1.8882x; 1.7264x over previous
#include <cuda_runtime.h>
#include <cstdint>

// ---------------------------------------------------------------------------
// SparseResUQueryNet R7: thread-per-item mask building + hit compaction.
//
// Keys: 28-bit ((t*256+x)*256+y)*256+z, t<16, coords in [1,250] (no byte
// carry under +-1 offsets). Pool keys: 25-bit (batch byte, b<2).
//
//  - bm1 (32MB) / bm2 (4MB): exact occupancy bitmaps.
//  - H1: small hash key->feature (8MB keys + 8MB payload, L2-resident),
//    probed only for non-self neighbor hits (~45k probes total).
//  - pooled rows indexed by rank2(pk) = prefix popcount over bm2 (3 micro
//    scan kernels over 1M words each launch).
//  - k_maskH / k_maskQ: THREAD-per-item 27-neighbor masks (18 independent
//    funnel-window loads -> high MLP, ~2.5 warp-instr/point issue cost).
//    k_maskQ writes full zero rows for no-hit points (58%) and warp-
//    aggregates hit points into a worklist; k_query runs hit points only.
//  - contested pool cells (~1%): rows pre-zeroed in k_maskH, pooled via
//    order-preserving-uint atomicMax, decoded on read in k_query.
// ---------------------------------------------------------------------------

#define FULL_MASK 0xFFFFFFFFu
#define H1_LOG 21
#define H1_SIZE (1u << H1_LOG)
#define H1_MASK (H1_SIZE - 1u)
#define EMPTY_KEY 0xFFFFFFFFu
#define BM1_WORDS (1u << 23)
#define BM2_WORDS (1u << 20)
#define CHUNK2 4096
#define NBLK2 (BM2_WORDS / CHUNK2)   // 256
#define NMAX  (1u << 20)

__device__ unsigned g_h1_keys[H1_SIZE];               // 8 MB
__device__ float    g_h1_feat[H1_SIZE];               // 8 MB
__device__ unsigned g_bm1[BM1_WORDS + 2];             // 32 MB (+pad)
__device__ unsigned g_bm2[BM2_WORDS + 2];             // 4 MB  (+pad)
__device__ unsigned g_cont[BM2_WORDS];                // 4 MB
__device__ unsigned g_pref2[BM2_WORDS];               // 4 MB
__device__ unsigned g_bsum2[NBLK2];
__device__ unsigned g_maskH[NMAX];                    // 4 MB
__device__ int      g_rowOf[NMAX];                    // 4 MB rank2 | cont<<31
__device__ float    g_pooled[(size_t)NMAX * 32];      // 128 MB
__device__ int      g_worklist[NMAX * 2];             // 8 MB
__device__ unsigned g_maskQ[NMAX * 2];                // 8 MB
__device__ int      g_wl_cnt;

// delta[d] = (dx<<16)+(dy<<8)+dz for d = (dx+1)*9+(dy+1)*3+(dz+1)
__constant__ unsigned c_delta[27] = {
    0xFFFEFEFFu, 0xFFFEFF00u, 0xFFFEFF01u,
    0xFFFEFFFFu, 0xFFFF0000u, 0xFFFF0001u,
    0xFFFF00FFu, 0xFFFF0100u, 0xFFFF0101u,
    0xFFFFFEFFu, 0xFFFFFF00u, 0xFFFFFF01u,
    0xFFFFFFFFu, 0x00000000u, 0x00000001u,
    0x000000FFu, 0x00000100u, 0x00000101u,
    0x0000FEFFu, 0x0000FF00u, 0x0000FF01u,
    0x0000FFFFu, 0x00010000u, 0x00010001u,
    0x000100FFu, 0x00010100u, 0x00010101u
};

__device__ __forceinline__ unsigned hash1(unsigned k) {
    return (k * 2654435761u) >> (32 - H1_LOG);
}
__device__ __forceinline__ unsigned encf(float f) {
    unsigned b = __float_as_uint(f);
    return b ^ (unsigned)(((int)b >> 31) | 0x80000000);
}
__device__ __forceinline__ float decf(unsigned u) {
    unsigned x = ((int)u < 0) ? (u ^ 0x80000000u) : ~u;
    return __uint_as_float(x);
}
// 3-bit window [bitpos, bitpos+2] (bitpos = neighbor-center key - 1).
__device__ __forceinline__ unsigned tri_at(const unsigned* bm, unsigned bitpos) {
    unsigned idx = bitpos >> 5, sh = bitpos & 31;
    return __funnelshift_r(bm[idx], bm[idx + 1], sh) & 7u;
}
// Full 27-bit neighbor mask for one key (18 independent loads).
__device__ __forceinline__ unsigned mask27(const unsigned* bm, unsigned key) {
    unsigned mask = 0;
#pragma unroll
    for (int g = 0; g < 9; g++)
        mask |= tri_at(bm, key + c_delta[g * 3]) << (g * 3);
    return mask;
}
__device__ __forceinline__ unsigned rank2_of(unsigned pk) {
    unsigned w = pk >> 5, b = pk & 31;
    return g_pref2[w] + __popc(g_bm2[w] & ((1u << b) - 1u));
}
__device__ __forceinline__ int nth_bit(unsigned mask, int lane) {
    unsigned mm = mask;
    for (int t = 0; t < lane; t++) mm &= mm - 1;
    return __ffs(mm) - 1;
}
__device__ __forceinline__ int block_scan_excl(int v, int tid) {
    __shared__ int sh[256];
    sh[tid] = v;
    __syncthreads();
    for (int off = 1; off < 256; off <<= 1) {
        int add = (tid >= off) ? sh[tid - off] : 0;
        __syncthreads();
        sh[tid] += add;
        __syncthreads();
    }
    int incl = sh[tid];
    __syncthreads();
    return incl - v;
}

// K0 -------------------------------------------------------------------------
__global__ void k_reset(const int4* __restrict__ hcoord,
                        const int* __restrict__ hbatch, int n) {
    int i = blockIdx.x * blockDim.x + threadIdx.x;
    int stride = gridDim.x * blockDim.x;
    for (unsigned s = (unsigned)i; s < H1_SIZE; s += stride)
        g_h1_keys[s] = EMPTY_KEY;
    if (i == 0) g_wl_cnt = 0;
    if (i >= n) return;
    int4 c = hcoord[i];  // t, x, y, z
    unsigned key = ((unsigned)c.x << 24) | ((unsigned)c.y << 16) |
                   ((unsigned)c.z << 8) | (unsigned)c.w;
    unsigned pk = ((unsigned)hbatch[i] << 24) | (key & 0x00FFFFFFu);
    g_bm1[key >> 5] = 0u;
    g_bm2[pk >> 5] = 0u;
    g_cont[pk >> 5] = 0u;
}

// K1 -------------------------------------------------------------------------
__global__ void k_insert(const float* __restrict__ hfeat,
                         const int4* __restrict__ hcoord,
                         const int* __restrict__ hbatch, int n) {
    int i = blockIdx.x * blockDim.x + threadIdx.x;
    if (i >= n) return;
    int4 c = hcoord[i];
    unsigned key = ((unsigned)c.x << 24) | ((unsigned)c.y << 16) |
                   ((unsigned)c.z << 8) | (unsigned)c.w;
    atomicOr(&g_bm1[key >> 5], 1u << (key & 31));
    unsigned s = hash1(key);
    while (true) {  // history keys unique (np.unique upstream)
        unsigned old = atomicCAS(&g_h1_keys[s], EMPTY_KEY, key);
        if (old == EMPTY_KEY) { g_h1_feat[s] = hfeat[i]; break; }
        s = (s + 1) & H1_MASK;
    }
    unsigned pk = ((unsigned)hbatch[i] << 24) | (key & 0x00FFFFFFu);
    unsigned bit = 1u << (pk & 31);
    unsigned prev = atomicOr(&g_bm2[pk >> 5], bit);
    if (prev & bit) atomicOr(&g_cont[pk >> 5], bit);
}

// bm2 prefix scan (3 micro passes) --------------------------------------------
__global__ void k_scanA() {
    int blk = blockIdx.x, tid = threadIdx.x;
    const uint4* bm = (const uint4*)g_bm2;
    size_t w4 = (size_t)blk * (CHUNK2 / 4) + (size_t)tid * 4;
    int s = 0;
#pragma unroll
    for (int j = 0; j < 4; j++) {
        uint4 v = bm[w4 + j];
        s += __popc(v.x) + __popc(v.y) + __popc(v.z) + __popc(v.w);
    }
    __shared__ int sh[256];
    sh[tid] = s;
    __syncthreads();
    for (int off = 128; off; off >>= 1) {
        if (tid < off) sh[tid] += sh[tid + off];
        __syncthreads();
    }
    if (tid == 0) g_bsum2[blk] = (unsigned)sh[0];
}
__global__ void k_scanB() {
    int tid = threadIdx.x;
    unsigned v = g_bsum2[tid];
    int ex = block_scan_excl((int)v, tid);
    g_bsum2[tid] = (unsigned)ex;
}
__global__ void k_scanC() {
    int blk = blockIdx.x, tid = threadIdx.x;
    size_t w0 = (size_t)blk * CHUNK2 + (size_t)tid * 16;
    unsigned wv[16];
    int s = 0;
#pragma unroll
    for (int j = 0; j < 16; j++) { wv[j] = g_bm2[w0 + j]; s += __popc(wv[j]); }
    int ex = block_scan_excl(s, tid);
    unsigned run = g_bsum2[blk] + (unsigned)ex;
#pragma unroll
    for (int j = 0; j < 16; j++) { g_pref2[w0 + j] = run; run += __popc(wv[j]); }
}

// K2: thread per voxel -------------------------------------------------------
__global__ void k_maskH(const int4* __restrict__ hcoord,
                        const int* __restrict__ hbatch, int n) {
    int i = blockIdx.x * blockDim.x + threadIdx.x;
    if (i >= n) return;
    int4 c = hcoord[i];
    unsigned key = ((unsigned)c.x << 24) | ((unsigned)c.y << 16) |
                   ((unsigned)c.z << 8) | (unsigned)c.w;
    g_maskH[i] = mask27(g_bm1, key);
    unsigned pk = ((unsigned)hbatch[i] << 24) | (key & 0x00FFFFFFu);
    unsigned r2 = rank2_of(pk);
    bool cont = (g_cont[pk >> 5] >> (pk & 31)) & 1u;
    g_rowOf[i] = (int)(r2 | (cont ? 0x80000000u : 0u));
    if (cont) {
        float* r = &g_pooled[(size_t)r2 * 32];
#pragma unroll
        for (int q = 0; q < 32; q++) r[q] = 0.0f;  // bits 0 = encoded minimum
    }
}

// K3: warp per voxel ----------------------------------------------------------
__global__ void __launch_bounds__(256)
k_bb_pool(const float* __restrict__ hfeat,
          const float* __restrict__ Wbb,
          const int4* __restrict__ hcoord, int n) {
    int w = (int)((blockIdx.x * blockDim.x + threadIdx.x) >> 5);
    int lane = threadIdx.x & 31;
    if (w >= n) return;
    unsigned mask = g_maskH[w];   // broadcast
    int rw = g_rowOf[w];          // broadcast
    unsigned row = (unsigned)rw & 0x7FFFFFFFu;
    bool cont = rw < 0;
    float acc;
    if (mask == (1u << 13)) {     // self-only: dominant fast path (~93%)
        acc = hfeat[w] * Wbb[13 * 32 + lane];
    } else {
        int4 c = hcoord[w];       // broadcast (L2-hot)
        unsigned key = ((unsigned)c.x << 24) | ((unsigned)c.y << 16) |
                       ((unsigned)c.z << 8) | (unsigned)c.w;
        int nhit = __popc(mask);
        float f = 0.0f;
        int d = 0;
        if (lane < nhit) {
            d = nth_bit(mask, lane);
            if (d == 13) {
                f = hfeat[w];
            } else {
                unsigned nk = key + c_delta[d];
                unsigned s = hash1(nk);
                while (g_h1_keys[s] != nk) s = (s + 1) & H1_MASK;  // present
                f = g_h1_feat[s];
            }
        }
        acc = 0.0f;
        for (int i = 0; i < nhit; i++) {  // ascending d == reference order
            float fd = __shfl_sync(FULL_MASK, f, i);
            int di = __shfl_sync(FULL_MASK, d, i);
            acc = fmaf(fd, Wbb[di * 32 + lane], acc);
        }
    }
    float* addr = &g_pooled[(size_t)row * 32 + lane];  // coalesced 128B
    if (cont) atomicMax((unsigned*)addr, encf(acc));
    else *addr = acc;
}

// K4: thread per query point ---------------------------------------------------
__global__ void k_maskQ(const float* __restrict__ points,
                        const int4* __restrict__ qcoord,
                        float* __restrict__ out, int npts) {
    int p = blockIdx.x * blockDim.x + threadIdx.x;
    bool active = p < npts;
    unsigned mask = 0;
    if (active) {
        int4 c = qcoord[p];  // b, x, y, z
        unsigned key = ((unsigned)c.x << 24) | ((unsigned)c.y << 16) |
                       ((unsigned)c.z << 8) | (unsigned)c.w;
        mask = mask27(g_bm2, key);
        g_maskQ[p] = mask;
    }
    bool hit = active && (mask != 0u);
    unsigned bal = __ballot_sync(FULL_MASK, hit);
    if (hit) {  // warp-aggregated worklist append
        int lane = threadIdx.x & 31;
        int leader = __ffs(bal) - 1;
        int base = 0;
        if (lane == leader) base = atomicAdd(&g_wl_cnt, __popc(bal));
        base = __shfl_sync(bal, base, leader);
        g_worklist[base + __popc(bal & ((1u << lane) - 1u))] = p;
    }
    if (active && !mask) {  // finalize no-hit rows here (58%)
        float4* o = (float4*)(out + (size_t)p * 36);
        const float* pt = points + (size_t)p * 5;
        o[0] = make_float4(pt[0], pt[1], pt[2], pt[3]);
        float4 z = make_float4(0.f, 0.f, 0.f, 0.f);
#pragma unroll
        for (int q = 1; q < 9; q++) o[q] = z;
    }
}

// K5: warp per HIT query point --------------------------------------------------
__global__ void __launch_bounds__(256)
k_query(const float* __restrict__ points,
        const float* __restrict__ Wc,
        const int4* __restrict__ qcoord,
        float* __restrict__ out, int npts) {
    int widx = (int)((blockIdx.x * blockDim.x + threadIdx.x) >> 5);
    int lane = threadIdx.x & 31;
    int cnt = g_wl_cnt;
    if (widx >= cnt) return;
    int p = g_worklist[widx];
    unsigned mask = g_maskQ[p];  // broadcast
    int4 c = qcoord[p];          // broadcast
    unsigned key = ((unsigned)c.x << 24) | ((unsigned)c.y << 16) |
                   ((unsigned)c.z << 8) | (unsigned)c.w;
    int nhit = __popc(mask);
    int d = 0, row = 0;
    bool cont = false;
    if (lane < nhit) {
        d = nth_bit(mask, lane);
        unsigned rk = key + c_delta[d];
        row = (int)rank2_of(rk);
        cont = (g_cont[rk >> 5] >> (rk & 31)) & 1u;
    }
    float acc = 0.0f;
    for (int i = 0; i < nhit; i++) {  // ascending d == reference order
        int rowi = __shfl_sync(FULL_MASK, row, i);
        int di = __shfl_sync(FULL_MASK, d, i);
        int conti = __shfl_sync(FULL_MASK, (int)cont, i);
        const float4* prow = (const float4*)&g_pooled[(size_t)rowi * 32];
        const float* wb = Wc + di * 1024 + lane;
#pragma unroll
        for (int q = 0; q < 8; q++) {
            float4 v = prow[q];  // uniform address -> broadcast
            if (conti) {
                v.x = decf(__float_as_uint(v.x));
                v.y = decf(__float_as_uint(v.y));
                v.z = decf(__float_as_uint(v.z));
                v.w = decf(__float_as_uint(v.w));
            }
            acc = fmaf(v.x, wb[(q * 4 + 0) * 32], acc);
            acc = fmaf(v.y, wb[(q * 4 + 1) * 32], acc);
            acc = fmaf(v.z, wb[(q * 4 + 2) * 32], acc);
            acc = fmaf(v.w, wb[(q * 4 + 3) * 32], acc);
        }
    }
    float* o = out + (size_t)p * 36;
    o[4 + lane] = acc;
    if (lane < 4) o[lane] = points[(size_t)p * 5 + lane];
}

// ---------------------------------------------------------------------------
extern "C" void kernel_launch(void* const* d_in, const int* in_sizes, int n_in,
                              void* d_out, int out_size) {
    const float* hfeat  = (const float*)d_in[0];
    const float* points = (const float*)d_in[1];
    const float* Wbb    = (const float*)d_in[2];
    const float* Wc     = (const float*)d_in[3];
    const int4*  hcoord = (const int4*)d_in[4];
    const int*   hbatch = (const int*)d_in[5];
    const int4*  qcoord = (const int4*)d_in[6];
    float* out = (float*)d_out;

    int n    = in_sizes[5];      // history voxel count
    int npts = in_sizes[6] / 4;  // query point count

    const int TB = 256;
    int nb  = (n + TB - 1) / TB;
    int qb  = (npts + TB - 1) / TB;
    int clr = ((int)H1_SIZE > n ? (int)H1_SIZE : n);
    k_reset<<<(clr + TB - 1) / TB, TB>>>(hcoord, hbatch, n);
    k_insert<<<nb, TB>>>(hfeat, hcoord, hbatch, n);
    k_scanA<<<NBLK2, TB>>>();
    k_scanB<<<1, TB>>>();
    k_scanC<<<NBLK2, TB>>>();
    k_maskH<<<nb, TB>>>(hcoord, hbatch, n);
    {
        long long tw = (long long)n * 32;
        k_bb_pool<<<(int)((tw + TB - 1) / TB), TB>>>(hfeat, Wbb, hcoord, n);
    }
    k_maskQ<<<qb, TB>>>(points, qcoord, out, npts);
    {
        long long tw = (long long)npts * 32;  // worst case; excess warps exit
        k_query<<<(int)((tw + TB - 1) / TB), TB>>>(points, Wc, qcoord, out, npts);
    }
}